// round 16
// baseline (speedup 1.0000x reference)
#include <cuda_runtime.h>
#include <cuda_pipeline.h>
#include <math.h>

#define VOCAB   50257
#define DIM     512
#define MAXDEP  20
#define NTOK    8192            // B*S; one single-warp CTA per token
#define PSTAGE  4               // smem row slots (2 pairs in flight)

__device__ float        g_partials[NTOK];
__device__ unsigned int g_count = 0;   // self-resets -> graph-replay safe

__global__ void __launch_bounds__(32) hs_kernel(
    const float* __restrict__ hidden,      // [NTOK, DIM]
    const float* __restrict__ node_emb,    // [VOCAB-1, DIM]
    const float* __restrict__ path_signs,  // [VOCAB, MAXDEP]
    const int*   __restrict__ targets,     // [NTOK]
    const int*   __restrict__ path_nodes,  // [VOCAB, MAXDEP]
    const int*   __restrict__ path_lens,   // [VOCAB]
    float*       __restrict__ out)
{
    __shared__ __align__(16) float s_rows[PSTAGE][DIM];   // 8 KB

    const int lane = threadIdx.x;          // 32-thread CTA = one warp
    const int tok  = blockIdx.x;

    const int t   = targets[tok];
    int       len = path_lens[t];
    if (len < 1) len = 1;

    // Coalesced preload of path metadata; broadcast via shfl at use sites.
    int   my_node = 0;
    float my_sign = 1.0f;
    if (lane < MAXDEP) {
        my_node = path_nodes[(size_t)t * MAXDEP + lane];
        my_sign = (path_signs[(size_t)t * MAXDEP + lane] >= 0.0f) ? 1.0f : -1.0f;
    }

    // Hidden row: 16 floats/lane in registers.
    const float4* h4 = reinterpret_cast<const float4*>(hidden + (size_t)tok * DIM);
    const float4 h0 = h4[lane];
    const float4 h1 = h4[lane + 32];
    const float4 h2 = h4[lane + 64];
    const float4 h3 = h4[lane + 96];

    // ---- Prologue: stage rows 0..3 (depth clamped to len-1 -> always finite).
    #pragma unroll
    for (int k = 0; k < PSTAGE; ++k) {
        const int dc   = (k < len) ? k : (len - 1);
        const int node = __shfl_sync(0xffffffffu, my_node, dc);
        const float4* g =
            reinterpret_cast<const float4*>(node_emb + (size_t)node * DIM);
        float4* s = reinterpret_cast<float4*>(&s_rows[k][0]);
        #pragma unroll
        for (int j = 0; j < 4; ++j)
            __pipeline_memcpy_async(&s[lane + 32 * j], &g[lane + 32 * j], 16);
        __pipeline_commit();
    }

    float nll = 0.0f;
    const int npairs = (len + 1) >> 1;     // warp-uniform, 1..10

    for (int p = 0; p < npairs; ++p) {
        const int d0 = 2 * p;
        const int d1 = 2 * p + 1;
        const int s0 = (p & 1) * 2;        // slots {0,1} / {2,3} alternate

        // Two oldest groups (rows d0, d1) complete when <= 2 remain pending.
        __pipeline_wait_prior(2);
        __syncwarp();

        // ---- depth d0: read + partial dot.
        const float4* w4a = reinterpret_cast<const float4*>(&s_rows[s0][0]);
        const float4 a0 = w4a[lane];
        const float4 a1 = w4a[lane + 32];
        const float4 a2 = w4a[lane + 64];
        const float4 a3 = w4a[lane + 96];

        float pa;
        pa = h0.x * a0.x;           pa = fmaf(h0.y, a0.y, pa);
        pa = fmaf(h0.z, a0.z, pa);  pa = fmaf(h0.w, a0.w, pa);
        pa = fmaf(h1.x, a1.x, pa);  pa = fmaf(h1.y, a1.y, pa);
        pa = fmaf(h1.z, a1.z, pa);  pa = fmaf(h1.w, a1.w, pa);
        pa = fmaf(h2.x, a2.x, pa);  pa = fmaf(h2.y, a2.y, pa);
        pa = fmaf(h2.z, a2.z, pa);  pa = fmaf(h2.w, a2.w, pa);
        pa = fmaf(h3.x, a3.x, pa);  pa = fmaf(h3.y, a3.y, pa);
        pa = fmaf(h3.z, a3.z, pa);  pa = fmaf(h3.w, a3.w, pa);

        // ---- depth d1 (clamped row already staged; masked below if past end).
        const float4* w4b = reinterpret_cast<const float4*>(&s_rows[s0 + 1][0]);
        const float4 b0 = w4b[lane];
        const float4 b1 = w4b[lane + 32];
        const float4 b2 = w4b[lane + 64];
        const float4 b3 = w4b[lane + 96];

        float pb;
        pb = h0.x * b0.x;           pb = fmaf(h0.y, b0.y, pb);
        pb = fmaf(h0.z, b0.z, pb);  pb = fmaf(h0.w, b0.w, pb);
        pb = fmaf(h1.x, b1.x, pb);  pb = fmaf(h1.y, b1.y, pb);
        pb = fmaf(h1.z, b1.z, pb);  pb = fmaf(h1.w, b1.w, pb);
        pb = fmaf(h2.x, b2.x, pb);  pb = fmaf(h2.y, b2.y, pb);
        pb = fmaf(h2.z, b2.z, pb);  pb = fmaf(h2.w, b2.w, pb);
        pb = fmaf(h3.x, b3.x, pb);  pb = fmaf(h3.y, b3.y, pb);
        pb = fmaf(h3.z, b3.z, pb);  pb = fmaf(h3.w, b3.w, pb);

        // ---- Refill both consumed slots for rows d0+4, d1+4 (clamped).
        {
            const int dc   = (d0 + 4 < len) ? (d0 + 4) : (len - 1);
            const int node = __shfl_sync(0xffffffffu, my_node, dc);
            const float4* g =
                reinterpret_cast<const float4*>(node_emb + (size_t)node * DIM);
            float4* s = reinterpret_cast<float4*>(&s_rows[s0][0]);
            #pragma unroll
            for (int j = 0; j < 4; ++j)
                __pipeline_memcpy_async(&s[lane + 32 * j], &g[lane + 32 * j], 16);
            __pipeline_commit();
        }
        {
            const int dc   = (d1 + 4 < len) ? (d1 + 4) : (len - 1);
            const int node = __shfl_sync(0xffffffffu, my_node, dc);
            const float4* g =
                reinterpret_cast<const float4*>(node_emb + (size_t)node * DIM);
            float4* s = reinterpret_cast<float4*>(&s_rows[s0 + 1][0]);
            #pragma unroll
            for (int j = 0; j < 4; ++j)
                __pipeline_memcpy_async(&s[lane + 32 * j], &g[lane + 32 * j], 16);
            __pipeline_commit();
        }

        // ---- Two independent butterflies, interleaved by the scheduler.
        #pragma unroll
        for (int off = 16; off > 0; off >>= 1) {
            pa += __shfl_xor_sync(0xffffffffu, pa, off);
            pb += __shfl_xor_sync(0xffffffffu, pb, off);
        }

        const float sa = __shfl_sync(0xffffffffu, my_sign, d0);
        const float za = sa * pa;
        nll += fmaxf(-za, 0.0f) + log1pf(expf(-fabsf(za)));

        if (d1 < len) {
            const float sb = __shfl_sync(0xffffffffu, my_sign, d1);
            const float zb = sb * pb;
            nll += fmaxf(-zb, 0.0f) + log1pf(expf(-fabsf(zb)));
        }
    }

    __pipeline_wait_prior(0);   // drain before exit

    if (lane == 0) g_partials[tok] = nll;
    __threadfence();

    // Last-block-done: one warp deterministically reduces all 8192 partials.
    __shared__ unsigned int s_last;
    if (lane == 0)
        s_last = (atomicAdd(&g_count, 1u) == (unsigned)(gridDim.x - 1));
    __syncwarp();
    const unsigned last = __shfl_sync(0xffffffffu, s_last, 0);

    if (last) {
        // 32 lanes x 64 float4 = 8192 floats; independent loads -> high MLP.
        const float4* p4 = reinterpret_cast<const float4*>(g_partials);
        float s = 0.0f;
        #pragma unroll
        for (int i = 0; i < NTOK / (32 * 4); ++i) {
            const float4 v = p4[lane + 32 * i];
            s += (v.x + v.y) + (v.z + v.w);
        }
        #pragma unroll
        for (int off = 16; off > 0; off >>= 1)
            s += __shfl_xor_sync(0xffffffffu, s, off);
        if (lane == 0) {
            out[0]  = s * (1.0f / (float)NTOK);
            g_count = 0;   // reset for next launch / graph replay
        }
    }
}

extern "C" void kernel_launch(void* const* d_in, const int* in_sizes, int n_in,
                              void* d_out, int out_size)
{
    const float* hidden     = (const float*)d_in[0];
    const float* node_emb   = (const float*)d_in[1];
    const float* path_signs = (const float*)d_in[2];
    const int*   targets    = (const int*)  d_in[3];
    const int*   path_nodes = (const int*)  d_in[4];
    const int*   path_lens  = (const int*)  d_in[5];
    float*       out        = (float*)d_out;

    hs_kernel<<<NTOK, 32>>>(hidden, node_emb, path_signs,
                            targets, path_nodes, path_lens, out);
}